// round 11
// baseline (speedup 1.0000x reference)
#include <cuda_runtime.h>
#include <cuda_fp16.h>

// Problem constants: N=100000, E=3200000, FEAT=128, HID=32, EMB=16
#define NMAX 100000
#define EMAX 3200000
#define SCAN_B 1024
#define NBLK ((NMAX + SCAN_B - 1) / SCAN_B)   // 98

// ---- scratch (device globals) ----
// rec1: per node 128B: slots0-7 = 32 fp16 h1 channels, slot8.x = als1 bits
__device__ __align__(128) uint2 g_rec1[NMAX * 16];
// rec2: per node 64B: slots0-3 = 16 fp16 h2 channels, slot4.x = als2 bits
__device__ __align__(128) uint2 g_rec2[NMAX * 8];
__device__ float g_ald1[NMAX];
__device__ float g_ald2[NMAX];

__device__ int g_deg [NMAX];
__device__ int g_scan[NMAX];
__device__ int g_off [NMAX];
__device__ int g_bsum [NBLK];
__device__ int g_bsumx[NBLK];
__device__ int g_cnt;
__device__ int g_rank[EMAX];
__device__ int g_esrc[EMAX];

__device__ __forceinline__ float leaky(float a) { return a > 0.0f ? a : 0.2f * a; }
__device__ __forceinline__ float2 h2f(unsigned b) {
    __half2 h = *reinterpret_cast<__half2*>(&b);
    return __half22float2(h);
}
__device__ __forceinline__ unsigned f2h2(float a, float b) {
    __half2 h = __floats2half2_rn(a, b);
    return *reinterpret_cast<unsigned*>(&h);
}

// ===========================================================================
// Fused hist + node1. Blocks [0, histB): degree histogram capturing edge
// ranks. Blocks [histB, ...): node1 GEMM -> packed rec1.
// ===========================================================================
__global__ __launch_bounds__(256) void hist_node1_kernel(
    const int* __restrict__ dst, int E,
    const float* __restrict__ x, const float* __restrict__ W1,
    const float* __restrict__ asrc, const float* __restrict__ adst, int N, int histB)
{
    if ((int)blockIdx.x < histB) {
        int t = blockIdx.x * 256 + threadIdx.x;
        int e = t * 4;
        if (e + 3 < E) {
            int4 d = *reinterpret_cast<const int4*>(dst + e);
            int4 r;
            r.x = atomicAdd(&g_deg[d.x], 1);
            r.y = atomicAdd(&g_deg[d.y], 1);
            r.z = atomicAdd(&g_deg[d.z], 1);
            r.w = atomicAdd(&g_deg[d.w], 1);
            *reinterpret_cast<int4*>(g_rank + e) = r;
        } else {
            for (; e < E; e++) g_rank[e] = atomicAdd(&g_deg[__ldg(dst + e)], 1);
        }
        return;
    }

    __shared__ float Ws[128 * 32];
    __shared__ float s_as[32], s_ad[32];
    for (int i = threadIdx.x; i < 128 * 32; i += 256) Ws[i] = W1[i];
    if (threadIdx.x < 32) { s_as[threadIdx.x] = asrc[threadIdx.x]; s_ad[threadIdx.x] = adst[threadIdx.x]; }
    __syncthreads();

    int n = (blockIdx.x - histB) * 256 + threadIdx.x;
    if (n >= N) return;

    float4 acc[8];
#pragma unroll
    for (int i = 0; i < 8; i++) acc[i] = make_float4(0.f, 0.f, 0.f, 0.f);

    const float4* xr = reinterpret_cast<const float4*>(x + (size_t)n * 128);
#pragma unroll 4
    for (int k4 = 0; k4 < 32; k4++) {
        float4 xv = __ldg(&xr[k4]);
        float xk[4] = {xv.x, xv.y, xv.z, xv.w};
#pragma unroll
        for (int kk = 0; kk < 4; kk++) {
            const float4* wr = reinterpret_cast<const float4*>(&Ws[(k4 * 4 + kk) * 32]);
            float xs = xk[kk];
#pragma unroll
            for (int c4 = 0; c4 < 8; c4++) {
                float4 w = wr[c4];
                acc[c4].x = fmaf(xs, w.x, acc[c4].x); acc[c4].y = fmaf(xs, w.y, acc[c4].y);
                acc[c4].z = fmaf(xs, w.z, acc[c4].z); acc[c4].w = fmaf(xs, w.w, acc[c4].w);
            }
        }
    }

    float als = 0.f, ald = 0.f;
#pragma unroll
    for (int c4 = 0; c4 < 8; c4++) {
        float4 a  = acc[c4];
        float4 s4 = reinterpret_cast<const float4*>(s_as)[c4];
        float4 d4 = reinterpret_cast<const float4*>(s_ad)[c4];
        als += a.x*s4.x + a.y*s4.y + a.z*s4.z + a.w*s4.w;
        ald += a.x*d4.x + a.y*d4.y + a.z*d4.z + a.w*d4.w;
    }
    g_ald1[n] = ald;

    uint2* rp = &g_rec1[(size_t)n * 16];
#pragma unroll
    for (int c4 = 0; c4 < 8; c4++) {
        uint2 r;
        r.x = f2h2(acc[c4].x, acc[c4].y);
        r.y = f2h2(acc[c4].z, acc[c4].w);
        rp[c4] = r;
    }
    rp[8] = make_uint2(__float_as_uint(als), 0u);
}

// ===========================================================================
// scan1: per-block inclusive scan + block sums; last block also scans sums.
// ===========================================================================
__global__ __launch_bounds__(SCAN_B) void scan1_kernel(int N, int nb) {
    __shared__ int sh[SCAN_B];
    int gid = blockIdx.x * SCAN_B + threadIdx.x;
    int v = (gid < N) ? g_deg[gid] : 0;
    sh[threadIdx.x] = v;
    __syncthreads();
#pragma unroll
    for (int o = 1; o < SCAN_B; o <<= 1) {
        int t = (threadIdx.x >= o) ? sh[threadIdx.x - o] : 0;
        __syncthreads();
        sh[threadIdx.x] += t;
        __syncthreads();
    }
    if (gid < N) g_scan[gid] = sh[threadIdx.x];
    __shared__ int s_last;
    if (threadIdx.x == SCAN_B - 1) {
        g_bsum[blockIdx.x] = sh[SCAN_B - 1];
        __threadfence();
        s_last = (atomicAdd(&g_cnt, 1) == nb - 1);
    }
    __syncthreads();
    if (s_last) {
        __shared__ int sb[128];
        int t = threadIdx.x;
        if (t < 128) {
            int bv = (t < nb) ? g_bsum[t] : 0;
            sb[t] = bv;
            __syncthreads();
#pragma unroll
            for (int o = 1; o < 128; o <<= 1) {
                int u = (t >= o) ? sb[t - o] : 0;
                __syncthreads();
                sb[t] += u;
                __syncthreads();
            }
            if (t < nb) g_bsumx[t] = sb[t] - bv;
        }
    }
}

__global__ __launch_bounds__(256) void scan3_kernel(int N) {
    int gid = blockIdx.x * 256 + threadIdx.x;
    if (gid < N)
        g_off[gid] = g_scan[gid] - g_deg[gid] + g_bsumx[gid / SCAN_B];
}

// ===========================================================================
// permute: atomic-free. p = off[dst[e]] + rank[e]; esrc[p] = src[e].
// ===========================================================================
__global__ __launch_bounds__(256) void permute_kernel(
    const int* __restrict__ src, const int* __restrict__ dst, int E)
{
    int t = blockIdx.x * 256 + threadIdx.x;
    int e = t * 4;
    if (e + 3 < E) {
        int4 d = *reinterpret_cast<const int4*>(dst + e);
        int4 r = *reinterpret_cast<const int4*>(g_rank + e);
        int4 s = *reinterpret_cast<const int4*>(src + e);
        int p0 = __ldg(&g_off[d.x]) + r.x;
        int p1 = __ldg(&g_off[d.y]) + r.y;
        int p2 = __ldg(&g_off[d.z]) + r.z;
        int p3 = __ldg(&g_off[d.w]) + r.w;
        g_esrc[p0] = s.x;
        g_esrc[p1] = s.y;
        g_esrc[p2] = s.z;
        g_esrc[p3] = s.w;
    } else {
        for (; e < E; e++) {
            int d = __ldg(dst + e);
            g_esrc[__ldg(&g_off[d]) + g_rank[e]] = __ldg(src + e);
        }
    }
}

// ===========================================================================
// agg1_node2 (fused): layer-1 aggregate using packed rec1 (single-wavefront
// row+als loads, redundant per-lane den -> no reductions), then in-block
// layer-2 GEMM, writing packed rec2.
// ===========================================================================
__global__ __launch_bounds__(256) void agg1_node2_kernel(
    const float* __restrict__ b1, const float* __restrict__ W2,
    const float* __restrict__ as2, const float* __restrict__ ad2, int N)
{
    __shared__ float s_hp1[16 * 36];   // 16 nodes x 32ch, stride 36 (16B-aligned rows)
    __shared__ float s_h2 [16 * 17];   // 16 nodes x 16ch
    __shared__ float s_als2[16];
    __shared__ float W2s[32 * 16];
    __shared__ float s_as2[16], s_ad2[16];
    for (int i = threadIdx.x; i < 32 * 16; i += 256) W2s[i] = W2[i];
    if (threadIdx.x < 16) { s_as2[threadIdx.x] = as2[threadIdx.x]; s_ad2[threadIdx.x] = ad2[threadIdx.x]; }

    int wid = blockIdx.x * 8 + (threadIdx.x >> 5);
    int lane = threadIdx.x & 31;
    int half = lane >> 4;
    int l16 = lane & 15;
    int lc = l16 < 8 ? l16 : 8;        // clamp: lanes 9-15 read slot 8 (same line)
    int n = wid * 2 + half;
    bool nvalid = (n < N);
    int nn = nvalid ? n : (N - 1);

    float ald = __ldg(&g_ald1[nn]);
    int start = g_off[nn];
    int deg = nvalid ? g_deg[nn] : 0;
    int end = start + deg;

    int nb = (deg + 15) >> 4;
    { int t = __shfl_xor_sync(0xffffffffu, nb, 16); nb = nb > t ? nb : t; }

    // prologue: srcs of block 0
    int s = 0;
    {
        int idx = start + l16;
        if (idx < end) s = __ldg(&g_esrc[idx]);
    }

    float4 acc = make_float4(0.f, 0.f, 0.f, 0.f);
    float den = 0.f;
    for (int b = 0; b < nb; b++) {
        // prefetch next block's srcs (coalesced)
        int idxn = start + (b + 1) * 16 + l16;
        int sN = 0;
        if (idxn < end) sN = __ldg(&g_esrc[idxn]);

        int base = start + b * 16;
        int mm = end - base;           // uniform within group
#pragma unroll
        for (int j = 0; j < 16; j += 4) {
            int s0 = __shfl_sync(0xffffffffu, s, j,     16);
            int s1 = __shfl_sync(0xffffffffu, s, j + 1, 16);
            int s2 = __shfl_sync(0xffffffffu, s, j + 2, 16);
            int s3 = __shfl_sync(0xffffffffu, s, j + 3, 16);
            uint2 v0 = __ldg(&g_rec1[s0 * 16 + lc]);
            uint2 v1 = __ldg(&g_rec1[s1 * 16 + lc]);
            uint2 v2 = __ldg(&g_rec1[s2 * 16 + lc]);
            uint2 v3 = __ldg(&g_rec1[s3 * 16 + lc]);
            float al0 = __uint_as_float(__shfl_sync(0xffffffffu, v0.x, 8, 16));
            float al1 = __uint_as_float(__shfl_sync(0xffffffffu, v1.x, 8, 16));
            float al2 = __uint_as_float(__shfl_sync(0xffffffffu, v2.x, 8, 16));
            float al3 = __uint_as_float(__shfl_sync(0xffffffffu, v3.x, 8, 16));
            float w0 = (j     < mm) ? __expf(leaky(al0 + ald)) : 0.f;
            float w1 = (j + 1 < mm) ? __expf(leaky(al1 + ald)) : 0.f;
            float w2 = (j + 2 < mm) ? __expf(leaky(al2 + ald)) : 0.f;
            float w3 = (j + 3 < mm) ? __expf(leaky(al3 + ald)) : 0.f;
            den += (w0 + w1) + (w2 + w3);
            float2 f0a = h2f(v0.x), f0b = h2f(v0.y);
            float2 f1a = h2f(v1.x), f1b = h2f(v1.y);
            float2 f2a = h2f(v2.x), f2b = h2f(v2.y);
            float2 f3a = h2f(v3.x), f3b = h2f(v3.y);
            acc.x = fmaf(w0, f0a.x, acc.x); acc.y = fmaf(w0, f0a.y, acc.y);
            acc.z = fmaf(w0, f0b.x, acc.z); acc.w = fmaf(w0, f0b.y, acc.w);
            acc.x = fmaf(w1, f1a.x, acc.x); acc.y = fmaf(w1, f1a.y, acc.y);
            acc.z = fmaf(w1, f1b.x, acc.z); acc.w = fmaf(w1, f1b.y, acc.w);
            acc.x = fmaf(w2, f2a.x, acc.x); acc.y = fmaf(w2, f2a.y, acc.y);
            acc.z = fmaf(w2, f2b.x, acc.z); acc.w = fmaf(w2, f2b.y, acc.w);
            acc.x = fmaf(w3, f3a.x, acc.x); acc.y = fmaf(w3, f3a.y, acc.y);
            acc.z = fmaf(w3, f3b.x, acc.z); acc.w = fmaf(w3, f3b.y, acc.w);
        }
        s = sN;
    }

    // self-loop from own record
    {
        uint2 vo = __ldg(&g_rec1[nn * 16 + lc]);
        float alo = __uint_as_float(__shfl_sync(0xffffffffu, vo.x, 8, 16));
        float ws = __expf(leaky(alo + ald));
        den += ws;
        float2 fa = h2f(vo.x), fb = h2f(vo.y);
        acc.x = fmaf(ws, fa.x, acc.x); acc.y = fmaf(ws, fa.y, acc.y);
        acc.z = fmaf(ws, fb.x, acc.z); acc.w = fmaf(ws, fb.y, acc.w);
    }

    float inv = 1.0f / (den + 1e-16f);
    int nloc = threadIdx.x >> 4;       // 0..15 local node index
    if (l16 < 8) {
        float4 bv = __ldg(&reinterpret_cast<const float4*>(b1)[l16]);
        float* row = &s_hp1[nloc * 36 + l16 * 4];
        row[0] = fmaxf(fmaf(acc.x, inv, bv.x), 0.f);
        row[1] = fmaxf(fmaf(acc.y, inv, bv.y), 0.f);
        row[2] = fmaxf(fmaf(acc.z, inv, bv.z), 0.f);
        row[3] = fmaxf(fmaf(acc.w, inv, bv.w), 0.f);
    }
    __syncthreads();

    // ---- phase 2: h2 = hp1 @ W2; als2/ald2. thread t: node t>>4, chan t&15.
    int o = threadIdx.x & 15;
    int n2 = blockIdx.x * 16 + nloc;
    if (n2 < N) {
        const float* row = &s_hp1[nloc * 36];
        float h2v = 0.f;
#pragma unroll
        for (int c = 0; c < 32; c++)
            h2v = fmaf(row[c], W2s[c * 16 + o], h2v);
        s_h2[nloc * 17 + o] = h2v;
        float pa = h2v * s_as2[o];
        float pd = h2v * s_ad2[o];
#pragma unroll
        for (int off = 8; off; off >>= 1) {
            pa += __shfl_xor_sync(0xffffffffu, pa, off, 16);
            pd += __shfl_xor_sync(0xffffffffu, pd, off, 16);
        }
        if (o == 0) { s_als2[nloc] = pa; g_ald2[n2] = pd; }
    }
    __syncthreads();

    // write packed rec2: 5 uint2 per node (4 channel slots + als2 slot)
    if (threadIdx.x < 80) {
        int node = threadIdx.x / 5;
        int slot = threadIdx.x % 5;
        int n2b = blockIdx.x * 16 + node;
        if (n2b < N) {
            uint2 r;
            if (slot < 4) {
                const float* rw = &s_h2[node * 17 + slot * 4];
                r.x = f2h2(rw[0], rw[1]);
                r.y = f2h2(rw[2], rw[3]);
            } else {
                r = make_uint2(__float_as_uint(s_als2[node]), 0u);
            }
            g_rec2[n2b * 8 + slot] = r;
        }
    }
}

// ===========================================================================
// agg2: layer-2 aggregate + output. FOUR nodes per warp, 8 lanes each,
// packed rec2 loads (single wavefront), redundant den, no reductions.
// ===========================================================================
__global__ __launch_bounds__(256) void agg2_kernel(
    const float* __restrict__ b2, float* __restrict__ out, int N)
{
    int wid = (blockIdx.x * 256 + threadIdx.x) >> 5;
    int lane = threadIdx.x & 31;
    int quad = lane >> 3;
    int l8 = lane & 7;
    int lc = l8 < 4 ? l8 : 4;          // clamp: lanes 5-7 read slot 4
    int n = wid * 4 + quad;
    if (wid * 4 >= N) return;
    bool nvalid = (n < N);
    int nn = nvalid ? n : (N - 1);

    float ald = __ldg(&g_ald2[nn]);
    int start = g_off[nn];
    int deg = nvalid ? g_deg[nn] : 0;
    int end = start + deg;

    int nb = (deg + 7) >> 3;
    { int t = __shfl_xor_sync(0xffffffffu, nb, 8);  nb = nb > t ? nb : t; }
    { int t = __shfl_xor_sync(0xffffffffu, nb, 16); nb = nb > t ? nb : t; }

    int s = 0;
    {
        int idx = start + l8;
        if (idx < end) s = __ldg(&g_esrc[idx]);
    }

    float4 acc = make_float4(0.f, 0.f, 0.f, 0.f);
    float den = 0.f;
    for (int b = 0; b < nb; b++) {
        int idxn = start + (b + 1) * 8 + l8;
        int sN = 0;
        if (idxn < end) sN = __ldg(&g_esrc[idxn]);

        int base = start + b * 8;
        int mm = end - base;
#pragma unroll
        for (int j = 0; j < 8; j += 4) {
            int s0 = __shfl_sync(0xffffffffu, s, j,     8);
            int s1 = __shfl_sync(0xffffffffu, s, j + 1, 8);
            int s2 = __shfl_sync(0xffffffffu, s, j + 2, 8);
            int s3 = __shfl_sync(0xffffffffu, s, j + 3, 8);
            uint2 v0 = __ldg(&g_rec2[s0 * 8 + lc]);
            uint2 v1 = __ldg(&g_rec2[s1 * 8 + lc]);
            uint2 v2 = __ldg(&g_rec2[s2 * 8 + lc]);
            uint2 v3 = __ldg(&g_rec2[s3 * 8 + lc]);
            float al0 = __uint_as_float(__shfl_sync(0xffffffffu, v0.x, 4, 8));
            float al1 = __uint_as_float(__shfl_sync(0xffffffffu, v1.x, 4, 8));
            float al2 = __uint_as_float(__shfl_sync(0xffffffffu, v2.x, 4, 8));
            float al3 = __uint_as_float(__shfl_sync(0xffffffffu, v3.x, 4, 8));
            float w0 = (j     < mm) ? __expf(leaky(al0 + ald)) : 0.f;
            float w1 = (j + 1 < mm) ? __expf(leaky(al1 + ald)) : 0.f;
            float w2 = (j + 2 < mm) ? __expf(leaky(al2 + ald)) : 0.f;
            float w3 = (j + 3 < mm) ? __expf(leaky(al3 + ald)) : 0.f;
            den += (w0 + w1) + (w2 + w3);
            float2 f0a = h2f(v0.x), f0b = h2f(v0.y);
            float2 f1a = h2f(v1.x), f1b = h2f(v1.y);
            float2 f2a = h2f(v2.x), f2b = h2f(v2.y);
            float2 f3a = h2f(v3.x), f3b = h2f(v3.y);
            acc.x = fmaf(w0, f0a.x, acc.x); acc.y = fmaf(w0, f0a.y, acc.y);
            acc.z = fmaf(w0, f0b.x, acc.z); acc.w = fmaf(w0, f0b.y, acc.w);
            acc.x = fmaf(w1, f1a.x, acc.x); acc.y = fmaf(w1, f1a.y, acc.y);
            acc.z = fmaf(w1, f1b.x, acc.z); acc.w = fmaf(w1, f1b.y, acc.w);
            acc.x = fmaf(w2, f2a.x, acc.x); acc.y = fmaf(w2, f2a.y, acc.y);
            acc.z = fmaf(w2, f2b.x, acc.z); acc.w = fmaf(w2, f2b.y, acc.w);
            acc.x = fmaf(w3, f3a.x, acc.x); acc.y = fmaf(w3, f3a.y, acc.y);
            acc.z = fmaf(w3, f3b.x, acc.z); acc.w = fmaf(w3, f3b.y, acc.w);
        }
        s = sN;
    }

    // self-loop
    {
        uint2 vo = __ldg(&g_rec2[nn * 8 + lc]);
        float alo = __uint_as_float(__shfl_sync(0xffffffffu, vo.x, 4, 8));
        float ws = __expf(leaky(alo + ald));
        den += ws;
        float2 fa = h2f(vo.x), fb = h2f(vo.y);
        acc.x = fmaf(ws, fa.x, acc.x); acc.y = fmaf(ws, fa.y, acc.y);
        acc.z = fmaf(ws, fb.x, acc.z); acc.w = fmaf(ws, fb.y, acc.w);
    }

    float inv = 1.0f / (den + 1e-16f);
    if (nvalid && l8 < 4) {
        float4 bv = __ldg(&reinterpret_cast<const float4*>(b2)[l8]);
        float4 r;
        r.x = fmaf(acc.x, inv, bv.x);
        r.y = fmaf(acc.y, inv, bv.y);
        r.z = fmaf(acc.z, inv, bv.z);
        r.w = fmaf(acc.w, inv, bv.w);
        reinterpret_cast<float4*>(&out[n * 16])[l8] = r;
    }
}

// ===========================================================================
extern "C" void kernel_launch(void* const* d_in, const int* in_sizes, int n_in,
                              void* d_out, int out_size)
{
    const float* x   = (const float*)d_in[0];
    const int*   ei  = (const int*)  d_in[1];
    const float* W1  = (const float*)d_in[3];
    const float* as1 = (const float*)d_in[4];
    const float* ad1 = (const float*)d_in[5];
    const float* b1  = (const float*)d_in[6];
    const float* W2  = (const float*)d_in[7];
    const float* as2 = (const float*)d_in[8];
    const float* ad2 = (const float*)d_in[9];
    const float* b2  = (const float*)d_in[10];

    int N = in_sizes[0] / 128;
    int E = in_sizes[1] / 2;
    const int* src = ei;
    const int* dst = ei + E;

    void* p_deg = nullptr; cudaGetSymbolAddress(&p_deg, g_deg);
    void* p_cnt = nullptr; cudaGetSymbolAddress(&p_cnt, g_cnt);
    cudaMemsetAsync(p_deg, 0, (size_t)N * sizeof(int));
    cudaMemsetAsync(p_cnt, 0, sizeof(int));

    int nblkN = (N + 255) / 256;
    int nblkE4 = (E / 4 + 256) / 256;
    int nscan = (N + SCAN_B - 1) / SCAN_B;

    hist_node1_kernel<<<nblkE4 + nblkN, 256>>>(dst, E, x, W1, as1, ad1, N, nblkE4);

    scan1_kernel<<<nscan, SCAN_B>>>(N, nscan);
    scan3_kernel<<<nblkN, 256>>>(N);
    permute_kernel<<<nblkE4, 256>>>(src, dst, E);

    agg1_node2_kernel<<<(N + 15) / 16, 256>>>(b1, W2, as2, ad2, N);

    int nwarp2 = (((N + 3) / 4) * 32 + 255) / 256;
    agg2_kernel<<<nwarp2, 256>>>(b2, (float*)d_out, N);
}

// round 12
// speedup vs baseline: 1.1977x; 1.1977x over previous
#include <cuda_runtime.h>
#include <cuda_fp16.h>

// Problem constants: N=100000, E=3200000, FEAT=128, HID=32, EMB=16
#define NMAX 100000
#define EMAX 3200000
#define SCAN_B 1024
#define NBLK ((NMAX + SCAN_B - 1) / SCAN_B)   // 98

// ---- scratch (device globals) ----
__device__ __half g_h1h[NMAX * 32];
__device__ float  g_hp1[NMAX * 32];
__device__ float  g_als1[NMAX], g_ald1[NMAX];
__device__ __half g_h2h[NMAX * 16];
__device__ float  g_als2[NMAX], g_ald2[NMAX];

__device__ int g_deg [NMAX];
__device__ int g_scan[NMAX];
__device__ int g_off [NMAX];
__device__ int g_bsum [NBLK];
__device__ int g_bsumx[NBLK];
__device__ int g_cnt;
__device__ unsigned short g_rank[EMAX];   // per-edge rank within dst group (deg << 65536)
__device__ int g_esrc[EMAX];

__device__ __forceinline__ float leaky(float a) { return a > 0.0f ? a : 0.2f * a; }
__device__ __forceinline__ float2 h2f(unsigned b) {
    __half2 h = *reinterpret_cast<__half2*>(&b);
    return __half22float2(h);
}

// ===========================================================================
// Fused hist + node1. Blocks [0, histB): degree histogram capturing edge
// ranks (u16). Blocks [histB, ...): node1 GEMM (fp32, one node per thread).
// ===========================================================================
__global__ __launch_bounds__(256) void hist_node1_kernel(
    const int* __restrict__ dst, int E,
    const float* __restrict__ x, const float* __restrict__ W1,
    const float* __restrict__ asrc, const float* __restrict__ adst, int N, int histB)
{
    if ((int)blockIdx.x < histB) {
        int t = blockIdx.x * 256 + threadIdx.x;
        int e = t * 4;
        if (e + 3 < E) {
            int4 d = *reinterpret_cast<const int4*>(dst + e);
            short4 r;
            r.x = (short)atomicAdd(&g_deg[d.x], 1);
            r.y = (short)atomicAdd(&g_deg[d.y], 1);
            r.z = (short)atomicAdd(&g_deg[d.z], 1);
            r.w = (short)atomicAdd(&g_deg[d.w], 1);
            *reinterpret_cast<short4*>(g_rank + e) = r;
        } else {
            for (; e < E; e++) g_rank[e] = (unsigned short)atomicAdd(&g_deg[__ldg(dst + e)], 1);
        }
        return;
    }

    __shared__ float Ws[128 * 32];
    __shared__ float s_as[32], s_ad[32];
    for (int i = threadIdx.x; i < 128 * 32; i += 256) Ws[i] = W1[i];
    if (threadIdx.x < 32) { s_as[threadIdx.x] = asrc[threadIdx.x]; s_ad[threadIdx.x] = adst[threadIdx.x]; }
    __syncthreads();

    int n = (blockIdx.x - histB) * 256 + threadIdx.x;
    if (n >= N) return;

    float4 acc[8];
#pragma unroll
    for (int i = 0; i < 8; i++) acc[i] = make_float4(0.f, 0.f, 0.f, 0.f);

    const float4* xr = reinterpret_cast<const float4*>(x + (size_t)n * 128);
#pragma unroll 4
    for (int k4 = 0; k4 < 32; k4++) {
        float4 xv = __ldg(&xr[k4]);
        float xk[4] = {xv.x, xv.y, xv.z, xv.w};
#pragma unroll
        for (int kk = 0; kk < 4; kk++) {
            const float4* wr = reinterpret_cast<const float4*>(&Ws[(k4 * 4 + kk) * 32]);
            float xs = xk[kk];
#pragma unroll
            for (int c4 = 0; c4 < 8; c4++) {
                float4 w = wr[c4];
                acc[c4].x = fmaf(xs, w.x, acc[c4].x); acc[c4].y = fmaf(xs, w.y, acc[c4].y);
                acc[c4].z = fmaf(xs, w.z, acc[c4].z); acc[c4].w = fmaf(xs, w.w, acc[c4].w);
            }
        }
    }

    float als = 0.f, ald = 0.f;
#pragma unroll
    for (int c4 = 0; c4 < 8; c4++) {
        float4 a  = acc[c4];
        float4 s4 = reinterpret_cast<const float4*>(s_as)[c4];
        float4 d4 = reinterpret_cast<const float4*>(s_ad)[c4];
        als += a.x*s4.x + a.y*s4.y + a.z*s4.z + a.w*s4.w;
        ald += a.x*d4.x + a.y*d4.y + a.z*d4.z + a.w*d4.w;
    }
    g_als1[n] = als; g_ald1[n] = ald;

    __half2* hp = reinterpret_cast<__half2*>(&g_h1h[n * 32]);
#pragma unroll
    for (int c4 = 0; c4 < 8; c4++) {
        hp[c4 * 2]     = __floats2half2_rn(acc[c4].x, acc[c4].y);
        hp[c4 * 2 + 1] = __floats2half2_rn(acc[c4].z, acc[c4].w);
    }
}

// ===========================================================================
// scan1: per-block inclusive scan + block sums; last block also scans sums.
// ===========================================================================
__global__ __launch_bounds__(SCAN_B) void scan1_kernel(int N, int nb) {
    __shared__ int sh[SCAN_B];
    int gid = blockIdx.x * SCAN_B + threadIdx.x;
    int v = (gid < N) ? g_deg[gid] : 0;
    sh[threadIdx.x] = v;
    __syncthreads();
#pragma unroll
    for (int o = 1; o < SCAN_B; o <<= 1) {
        int t = (threadIdx.x >= o) ? sh[threadIdx.x - o] : 0;
        __syncthreads();
        sh[threadIdx.x] += t;
        __syncthreads();
    }
    if (gid < N) g_scan[gid] = sh[threadIdx.x];
    __shared__ int s_last;
    if (threadIdx.x == SCAN_B - 1) {
        g_bsum[blockIdx.x] = sh[SCAN_B - 1];
        __threadfence();
        s_last = (atomicAdd(&g_cnt, 1) == nb - 1);
    }
    __syncthreads();
    if (s_last) {
        __shared__ int sb[128];
        int t = threadIdx.x;
        if (t < 128) {
            int bv = (t < nb) ? g_bsum[t] : 0;
            sb[t] = bv;
            __syncthreads();
#pragma unroll
            for (int o = 1; o < 128; o <<= 1) {
                int u = (t >= o) ? sb[t - o] : 0;
                __syncthreads();
                sb[t] += u;
                __syncthreads();
            }
            if (t < nb) g_bsumx[t] = sb[t] - bv;
        }
    }
}

__global__ __launch_bounds__(256) void scan3_kernel(int N) {
    int gid = blockIdx.x * 256 + threadIdx.x;
    if (gid < N)
        g_off[gid] = g_scan[gid] - g_deg[gid] + g_bsumx[gid / SCAN_B];
}

// ===========================================================================
// permute: atomic-free. p = off[dst[e]] + rank[e]; esrc[p] = src[e].
// ===========================================================================
__global__ __launch_bounds__(256) void permute_kernel(
    const int* __restrict__ src, const int* __restrict__ dst, int E)
{
    int t = blockIdx.x * 256 + threadIdx.x;
    int e = t * 4;
    if (e + 3 < E) {
        int4 d = *reinterpret_cast<const int4*>(dst + e);
        short4 r = *reinterpret_cast<const short4*>(g_rank + e);
        int4 s = *reinterpret_cast<const int4*>(src + e);
        int p0 = __ldg(&g_off[d.x]) + (int)(unsigned short)r.x;
        int p1 = __ldg(&g_off[d.y]) + (int)(unsigned short)r.y;
        int p2 = __ldg(&g_off[d.z]) + (int)(unsigned short)r.z;
        int p3 = __ldg(&g_off[d.w]) + (int)(unsigned short)r.w;
        g_esrc[p0] = s.x;
        g_esrc[p1] = s.y;
        g_esrc[p2] = s.z;
        g_esrc[p3] = s.w;
    } else {
        for (; e < E; e++) {
            int d = __ldg(dst + e);
            g_esrc[__ldg(&g_off[d]) + (int)g_rank[e]] = __ldg(src + e);
        }
    }
}

// ===========================================================================
// agg1: layer-1 aggregate. FOUR nodes per warp, 8 lanes each (uint2 row
// loads = 4 channels/lane). w computed per-lane in the load phase (one exp
// warp-instr per 32 edges), pipelined.
// ===========================================================================
__global__ __launch_bounds__(256) void agg1_kernel(const float* __restrict__ b1, int N)
{
    int wid = (blockIdx.x * 256 + threadIdx.x) >> 5;
    int lane = threadIdx.x & 31;
    int quad = lane >> 3;          // node within warp (0..3)
    int l8 = lane & 7;             // channel-quad index (0..7)
    int n = wid * 4 + quad;
    if (wid * 4 >= N) return;
    bool nvalid = (n < N);
    int nn = nvalid ? n : (N - 1);

    float ald = __ldg(&g_ald1[nn]);
    int start = g_off[nn];
    int deg = g_deg[nn];
    int end = start + deg;

    int nb = (deg + 7) >> 3;
    { int t = __shfl_xor_sync(0xffffffffu, nb, 8);  nb = nb > t ? nb : t; }
    { int t = __shfl_xor_sync(0xffffffffu, nb, 16); nb = nb > t ? nb : t; }

    // prologue: block 0 (per-lane edge)
    int s = 0; float w;
    {
        int idx = start + l8;
        bool v = nvalid && idx < end;
        float al = 0.f;
        if (v) { s = __ldg(&g_esrc[idx]); al = __ldg(&g_als1[s]); }
        w = v ? __expf(leaky(al + ald)) : 0.f;
    }

    float4 acc = make_float4(0.f, 0.f, 0.f, 0.f);
    float den = 0.f;
    const uint2* h1u = reinterpret_cast<const uint2*>(g_h1h);   // 8 uint2 per node
    for (int b = 0; b < nb; b++) {
        int idx2 = start + (b + 1) * 8 + l8;
        bool v2 = nvalid && idx2 < end;
        int s2 = 0; float al2 = 0.f;
        if (v2) { s2 = __ldg(&g_esrc[idx2]); al2 = __ldg(&g_als1[s2]); }

        den += w;
#pragma unroll
        for (int j = 0; j < 8; j += 4) {
            int   s0 = __shfl_sync(0xffffffffu, s, j,     8);
            int   s1 = __shfl_sync(0xffffffffu, s, j + 1, 8);
            int   s2b= __shfl_sync(0xffffffffu, s, j + 2, 8);
            int   s3 = __shfl_sync(0xffffffffu, s, j + 3, 8);
            float w0 = __shfl_sync(0xffffffffu, w, j,     8);
            float w1 = __shfl_sync(0xffffffffu, w, j + 1, 8);
            float w2 = __shfl_sync(0xffffffffu, w, j + 2, 8);
            float w3 = __shfl_sync(0xffffffffu, w, j + 3, 8);
            uint2 v0 = __ldg(&h1u[s0 * 8 + l8]);
            uint2 v1 = __ldg(&h1u[s1 * 8 + l8]);
            uint2 v2b= __ldg(&h1u[s2b* 8 + l8]);
            uint2 v3 = __ldg(&h1u[s3 * 8 + l8]);
            float2 f0a = h2f(v0.x), f0b = h2f(v0.y);
            float2 f1a = h2f(v1.x), f1b = h2f(v1.y);
            float2 f2a = h2f(v2b.x), f2b = h2f(v2b.y);
            float2 f3a = h2f(v3.x), f3b = h2f(v3.y);
            acc.x = fmaf(w0, f0a.x, acc.x); acc.y = fmaf(w0, f0a.y, acc.y);
            acc.z = fmaf(w0, f0b.x, acc.z); acc.w = fmaf(w0, f0b.y, acc.w);
            acc.x = fmaf(w1, f1a.x, acc.x); acc.y = fmaf(w1, f1a.y, acc.y);
            acc.z = fmaf(w1, f1b.x, acc.z); acc.w = fmaf(w1, f1b.y, acc.w);
            acc.x = fmaf(w2, f2a.x, acc.x); acc.y = fmaf(w2, f2a.y, acc.y);
            acc.z = fmaf(w2, f2b.x, acc.z); acc.w = fmaf(w2, f2b.y, acc.w);
            acc.x = fmaf(w3, f3a.x, acc.x); acc.y = fmaf(w3, f3a.y, acc.y);
            acc.z = fmaf(w3, f3b.x, acc.z); acc.w = fmaf(w3, f3b.y, acc.w);
        }
        s = s2;
        w = v2 ? __expf(leaky(al2 + ald)) : 0.f;
    }
#pragma unroll
    for (int o = 4; o; o >>= 1) den += __shfl_xor_sync(0xffffffffu, den, o, 8);

    float wself = __expf(leaky(__ldg(&g_als1[nn]) + ald));
    den += wself;
    {
        uint2 vo = __ldg(&h1u[nn * 8 + l8]);
        float2 fa = h2f(vo.x), fb = h2f(vo.y);
        acc.x = fmaf(wself, fa.x, acc.x); acc.y = fmaf(wself, fa.y, acc.y);
        acc.z = fmaf(wself, fb.x, acc.z); acc.w = fmaf(wself, fb.y, acc.w);
    }

    float inv = 1.0f / (den + 1e-16f);
    if (nvalid) {
        float4 bv = __ldg(&reinterpret_cast<const float4*>(b1)[l8]);
        float4 r;
        r.x = fmaxf(fmaf(acc.x, inv, bv.x), 0.f);
        r.y = fmaxf(fmaf(acc.y, inv, bv.y), 0.f);
        r.z = fmaxf(fmaf(acc.z, inv, bv.z), 0.f);
        r.w = fmaxf(fmaf(acc.w, inv, bv.w), 0.f);
        reinterpret_cast<float4*>(&g_hp1[n * 32])[l8] = r;
    }
}

// ===========================================================================
// node2: h2 = h' @ W2 (-> fp16); al_s2/al_d2
// ===========================================================================
__global__ __launch_bounds__(256) void node2_kernel(
    const float* __restrict__ W2,
    const float* __restrict__ asrc, const float* __restrict__ adst, int N)
{
    __shared__ float Ws[32 * 16];
    __shared__ float s_as[16], s_ad[16];
    for (int i = threadIdx.x; i < 32 * 16; i += 256) Ws[i] = W2[i];
    if (threadIdx.x < 16) { s_as[threadIdx.x] = asrc[threadIdx.x]; s_ad[threadIdx.x] = adst[threadIdx.x]; }
    __syncthreads();

    int n = blockIdx.x * 256 + threadIdx.x;
    if (n >= N) return;

    float4 h2[4];
#pragma unroll
    for (int i = 0; i < 4; i++) h2[i] = make_float4(0.f, 0.f, 0.f, 0.f);

    const float4* hp = reinterpret_cast<const float4*>(&g_hp1[n * 32]);
#pragma unroll
    for (int c4 = 0; c4 < 8; c4++) {
        float4 xv = hp[c4];
        float xk[4] = {xv.x, xv.y, xv.z, xv.w};
#pragma unroll
        for (int kk = 0; kk < 4; kk++) {
            const float4* wr = reinterpret_cast<const float4*>(&Ws[(c4 * 4 + kk) * 16]);
            float xs = xk[kk];
#pragma unroll
            for (int o4 = 0; o4 < 4; o4++) {
                float4 w = wr[o4];
                h2[o4].x = fmaf(xs, w.x, h2[o4].x); h2[o4].y = fmaf(xs, w.y, h2[o4].y);
                h2[o4].z = fmaf(xs, w.z, h2[o4].z); h2[o4].w = fmaf(xs, w.w, h2[o4].w);
            }
        }
    }

    float als = 0.f, ald = 0.f;
#pragma unroll
    for (int o4 = 0; o4 < 4; o4++) {
        float4 a  = h2[o4];
        float4 s4 = reinterpret_cast<const float4*>(s_as)[o4];
        float4 d4 = reinterpret_cast<const float4*>(s_ad)[o4];
        als += a.x*s4.x + a.y*s4.y + a.z*s4.z + a.w*s4.w;
        ald += a.x*d4.x + a.y*d4.y + a.z*d4.z + a.w*d4.w;
    }
    g_als2[n] = als; g_ald2[n] = ald;

    __half2* out = reinterpret_cast<__half2*>(&g_h2h[n * 16]);
#pragma unroll
    for (int o4 = 0; o4 < 4; o4++) {
        out[o4 * 2]     = __floats2half2_rn(h2[o4].x, h2[o4].y);
        out[o4 * 2 + 1] = __floats2half2_rn(h2[o4].z, h2[o4].w);
    }
}

// ===========================================================================
// agg2: layer-2 aggregate + output. EIGHT nodes per warp, 4 lanes each
// (uint2 row loads = 4 channels/lane), pipelined.
// ===========================================================================
__global__ __launch_bounds__(256) void agg2_kernel(
    const float* __restrict__ b2, float* __restrict__ out, int N)
{
    int wid = (blockIdx.x * 256 + threadIdx.x) >> 5;
    int lane = threadIdx.x & 31;
    int oct = lane >> 2;           // node within warp (0..7)
    int l4 = lane & 3;             // channel-quad index (0..3)
    int n = wid * 8 + oct;
    if (wid * 8 >= N) return;
    bool nvalid = (n < N);
    int nn = nvalid ? n : (N - 1);

    float ald = __ldg(&g_ald2[nn]);
    int start = g_off[nn];
    int deg = g_deg[nn];
    int end = start + deg;

    int nb = (deg + 3) >> 2;
    { int t = __shfl_xor_sync(0xffffffffu, nb, 4);  nb = nb > t ? nb : t; }
    { int t = __shfl_xor_sync(0xffffffffu, nb, 8);  nb = nb > t ? nb : t; }
    { int t = __shfl_xor_sync(0xffffffffu, nb, 16); nb = nb > t ? nb : t; }

    int s = 0; float w;
    {
        int idx = start + l4;
        bool v = nvalid && idx < end;
        float al = 0.f;
        if (v) { s = __ldg(&g_esrc[idx]); al = __ldg(&g_als2[s]); }
        w = v ? __expf(leaky(al + ald)) : 0.f;
    }

    float4 acc = make_float4(0.f, 0.f, 0.f, 0.f);
    float den = 0.f;
    const uint2* h2u = reinterpret_cast<const uint2*>(g_h2h);   // 4 uint2 per node
    for (int b = 0; b < nb; b++) {
        int idx2 = start + (b + 1) * 4 + l4;
        bool v2 = nvalid && idx2 < end;
        int s2 = 0; float al2 = 0.f;
        if (v2) { s2 = __ldg(&g_esrc[idx2]); al2 = __ldg(&g_als2[s2]); }

        den += w;
        {
            int   s0 = __shfl_sync(0xffffffffu, s, 0, 4);
            int   s1 = __shfl_sync(0xffffffffu, s, 1, 4);
            int   s2b= __shfl_sync(0xffffffffu, s, 2, 4);
            int   s3 = __shfl_sync(0xffffffffu, s, 3, 4);
            float w0 = __shfl_sync(0xffffffffu, w, 0, 4);
            float w1 = __shfl_sync(0xffffffffu, w, 1, 4);
            float w2 = __shfl_sync(0xffffffffu, w, 2, 4);
            float w3 = __shfl_sync(0xffffffffu, w, 3, 4);
            uint2 v0 = __ldg(&h2u[s0 * 4 + l4]);
            uint2 v1 = __ldg(&h2u[s1 * 4 + l4]);
            uint2 v2b= __ldg(&h2u[s2b* 4 + l4]);
            uint2 v3 = __ldg(&h2u[s3 * 4 + l4]);
            float2 f0a = h2f(v0.x), f0b = h2f(v0.y);
            float2 f1a = h2f(v1.x), f1b = h2f(v1.y);
            float2 f2a = h2f(v2b.x), f2b = h2f(v2b.y);
            float2 f3a = h2f(v3.x), f3b = h2f(v3.y);
            acc.x = fmaf(w0, f0a.x, acc.x); acc.y = fmaf(w0, f0a.y, acc.y);
            acc.z = fmaf(w0, f0b.x, acc.z); acc.w = fmaf(w0, f0b.y, acc.w);
            acc.x = fmaf(w1, f1a.x, acc.x); acc.y = fmaf(w1, f1a.y, acc.y);
            acc.z = fmaf(w1, f1b.x, acc.z); acc.w = fmaf(w1, f1b.y, acc.w);
            acc.x = fmaf(w2, f2a.x, acc.x); acc.y = fmaf(w2, f2a.y, acc.y);
            acc.z = fmaf(w2, f2b.x, acc.z); acc.w = fmaf(w2, f2b.y, acc.w);
            acc.x = fmaf(w3, f3a.x, acc.x); acc.y = fmaf(w3, f3a.y, acc.y);
            acc.z = fmaf(w3, f3b.x, acc.z); acc.w = fmaf(w3, f3b.y, acc.w);
        }
        s = s2;
        w = v2 ? __expf(leaky(al2 + ald)) : 0.f;
    }
#pragma unroll
    for (int o = 2; o; o >>= 1) den += __shfl_xor_sync(0xffffffffu, den, o, 4);

    float wself = __expf(leaky(__ldg(&g_als2[nn]) + ald));
    den += wself;
    {
        uint2 vo = __ldg(&h2u[nn * 4 + l4]);
        float2 fa = h2f(vo.x), fb = h2f(vo.y);
        acc.x = fmaf(wself, fa.x, acc.x); acc.y = fmaf(wself, fa.y, acc.y);
        acc.z = fmaf(wself, fb.x, acc.z); acc.w = fmaf(wself, fb.y, acc.w);
    }

    float inv = 1.0f / (den + 1e-16f);
    if (nvalid) {
        float4 bv = __ldg(&reinterpret_cast<const float4*>(b2)[l4]);
        float4 r;
        r.x = fmaf(acc.x, inv, bv.x);
        r.y = fmaf(acc.y, inv, bv.y);
        r.z = fmaf(acc.z, inv, bv.z);
        r.w = fmaf(acc.w, inv, bv.w);
        reinterpret_cast<float4*>(&out[n * 16])[l4] = r;
    }
}

// ===========================================================================
extern "C" void kernel_launch(void* const* d_in, const int* in_sizes, int n_in,
                              void* d_out, int out_size)
{
    const float* x   = (const float*)d_in[0];
    const int*   ei  = (const int*)  d_in[1];
    const float* W1  = (const float*)d_in[3];
    const float* as1 = (const float*)d_in[4];
    const float* ad1 = (const float*)d_in[5];
    const float* b1  = (const float*)d_in[6];
    const float* W2  = (const float*)d_in[7];
    const float* as2 = (const float*)d_in[8];
    const float* ad2 = (const float*)d_in[9];
    const float* b2  = (const float*)d_in[10];

    int N = in_sizes[0] / 128;
    int E = in_sizes[1] / 2;
    const int* src = ei;
    const int* dst = ei + E;

    void* p_deg = nullptr; cudaGetSymbolAddress(&p_deg, g_deg);
    void* p_cnt = nullptr; cudaGetSymbolAddress(&p_cnt, g_cnt);
    cudaMemsetAsync(p_deg, 0, (size_t)N * sizeof(int));
    cudaMemsetAsync(p_cnt, 0, sizeof(int));

    int nblkN = (N + 255) / 256;
    int nblkE4 = (E / 4 + 256) / 256;
    int nscan = (N + SCAN_B - 1) / SCAN_B;

    hist_node1_kernel<<<nblkE4 + nblkN, 256>>>(dst, E, x, W1, as1, ad1, N, nblkE4);

    scan1_kernel<<<nscan, SCAN_B>>>(N, nscan);
    scan3_kernel<<<nblkN, 256>>>(N);
    permute_kernel<<<nblkE4, 256>>>(src, dst, E);

    int nwarp1 = (((N + 3) / 4) * 32 + 255) / 256;
    agg1_kernel<<<nwarp1, 256>>>(b1, N);

    node2_kernel<<<nblkN, 256>>>(W2, as2, ad2, N);

    int nwarp2 = (((N + 7) / 8) * 32 + 255) / 256;
    agg2_kernel<<<nwarp2, 256>>>(b2, (float*)d_out, N);
}

// round 13
// speedup vs baseline: 1.2796x; 1.0684x over previous
#include <cuda_runtime.h>
#include <cuda_fp16.h>

// Problem constants: N=100000, E=3200000, FEAT=128, HID=32, EMB=16
#define NMAX 100000
#define EMAX 3200000
#define SCAN_B 1024
#define NBLK ((NMAX + SCAN_B - 1) / SCAN_B)   // 98

// ---- scratch (device globals) ----
__device__ __align__(16) __half g_h1h[NMAX * 32];
__device__ float  g_hp1[NMAX * 32];
__device__ float  g_als1[NMAX], g_ald1[NMAX];
__device__ __align__(16) __half g_h2h[NMAX * 16];
__device__ float  g_als2[NMAX], g_ald2[NMAX];

__device__ int g_deg [NMAX + 1];      // [NMAX] = scan arrive counter (memset with deg)
__device__ int g_off [NMAX];
__device__ int g_bsum [NBLK];
__device__ unsigned short g_rank[EMAX];
__device__ int g_esrc[EMAX];

__device__ __forceinline__ float leaky(float a) { return a > 0.0f ? a : 0.2f * a; }
__device__ __forceinline__ float2 h2f(unsigned b) {
    __half2 h = *reinterpret_cast<__half2*>(&b);
    return __half22float2(h);
}

// ===========================================================================
// Fused hist + node1. Blocks [0, histB): degree histogram capturing edge
// ranks (u16). Blocks [histB, ...): node1 GEMM (fp32, one node per thread).
// ===========================================================================
__global__ __launch_bounds__(256) void hist_node1_kernel(
    const int* __restrict__ dst, int E,
    const float* __restrict__ x, const float* __restrict__ W1,
    const float* __restrict__ asrc, const float* __restrict__ adst, int N, int histB)
{
    if ((int)blockIdx.x < histB) {
        int t = blockIdx.x * 256 + threadIdx.x;
        int e = t * 4;
        if (e + 3 < E) {
            int4 d = *reinterpret_cast<const int4*>(dst + e);
            short4 r;
            r.x = (short)atomicAdd(&g_deg[d.x], 1);
            r.y = (short)atomicAdd(&g_deg[d.y], 1);
            r.z = (short)atomicAdd(&g_deg[d.z], 1);
            r.w = (short)atomicAdd(&g_deg[d.w], 1);
            *reinterpret_cast<short4*>(g_rank + e) = r;
        } else {
            for (; e < E; e++) g_rank[e] = (unsigned short)atomicAdd(&g_deg[__ldg(dst + e)], 1);
        }
        return;
    }

    __shared__ float Ws[128 * 32];
    __shared__ float s_as[32], s_ad[32];
    for (int i = threadIdx.x; i < 128 * 32; i += 256) Ws[i] = W1[i];
    if (threadIdx.x < 32) { s_as[threadIdx.x] = asrc[threadIdx.x]; s_ad[threadIdx.x] = adst[threadIdx.x]; }
    __syncthreads();

    int n = (blockIdx.x - histB) * 256 + threadIdx.x;
    if (n >= N) return;

    float4 acc[8];
#pragma unroll
    for (int i = 0; i < 8; i++) acc[i] = make_float4(0.f, 0.f, 0.f, 0.f);

    const float4* xr = reinterpret_cast<const float4*>(x + (size_t)n * 128);
#pragma unroll 4
    for (int k4 = 0; k4 < 32; k4++) {
        float4 xv = __ldg(&xr[k4]);
        float xk[4] = {xv.x, xv.y, xv.z, xv.w};
#pragma unroll
        for (int kk = 0; kk < 4; kk++) {
            const float4* wr = reinterpret_cast<const float4*>(&Ws[(k4 * 4 + kk) * 32]);
            float xs = xk[kk];
#pragma unroll
            for (int c4 = 0; c4 < 8; c4++) {
                float4 w = wr[c4];
                acc[c4].x = fmaf(xs, w.x, acc[c4].x); acc[c4].y = fmaf(xs, w.y, acc[c4].y);
                acc[c4].z = fmaf(xs, w.z, acc[c4].z); acc[c4].w = fmaf(xs, w.w, acc[c4].w);
            }
        }
    }

    float als = 0.f, ald = 0.f;
#pragma unroll
    for (int c4 = 0; c4 < 8; c4++) {
        float4 a  = acc[c4];
        float4 s4 = reinterpret_cast<const float4*>(s_as)[c4];
        float4 d4 = reinterpret_cast<const float4*>(s_ad)[c4];
        als += a.x*s4.x + a.y*s4.y + a.z*s4.z + a.w*s4.w;
        ald += a.x*d4.x + a.y*d4.y + a.z*d4.z + a.w*d4.w;
    }
    g_als1[n] = als; g_ald1[n] = ald;

    __half2* hp = reinterpret_cast<__half2*>(&g_h1h[n * 32]);
#pragma unroll
    for (int c4 = 0; c4 < 8; c4++) {
        hp[c4 * 2]     = __floats2half2_rn(acc[c4].x, acc[c4].y);
        hp[c4 * 2 + 1] = __floats2half2_rn(acc[c4].z, acc[c4].w);
    }
}

// ===========================================================================
// Fused scan: per-block inclusive scan, publish block sum, grid arrive+spin
// (98 blocks <= 148 SMs, all resident -> spin is safe), then each block adds
// its prefix of block sums and writes g_off directly. One kernel, one pass.
// ===========================================================================
__global__ __launch_bounds__(SCAN_B) void scan_kernel(int N, int nb) {
    __shared__ int sh[SCAN_B];
    __shared__ int red[128];
    int b = blockIdx.x;
    int gid = b * SCAN_B + threadIdx.x;
    int v = (gid < N) ? g_deg[gid] : 0;
    sh[threadIdx.x] = v;
    __syncthreads();
#pragma unroll
    for (int o = 1; o < SCAN_B; o <<= 1) {
        int t = (threadIdx.x >= o) ? sh[threadIdx.x - o] : 0;
        __syncthreads();
        sh[threadIdx.x] += t;
        __syncthreads();
    }
    if (threadIdx.x == SCAN_B - 1) {
        g_bsum[b] = sh[SCAN_B - 1];
        __threadfence();
        atomicAdd(&g_deg[NMAX], 1);
    }
    if (threadIdx.x == 0) {
        while (((volatile int*)g_deg)[NMAX] < nb) { }
    }
    __syncthreads();
    __threadfence();   // acquire: order bsum reads after counter observation

    // exclusive prefix of block sums for this block (nb <= 128)
    int t = threadIdx.x;
    if (t < 128) red[t] = (t < b) ? g_bsum[t] : 0;
    __syncthreads();
    if (t < 64) red[t] += red[t + 64];
    __syncthreads();
    if (t < 32) {
        int s = red[t] + red[t + 32];
#pragma unroll
        for (int o = 16; o; o >>= 1) s += __shfl_xor_sync(0xffffffffu, s, o);
        if (t == 0) red[0] = s;
    }
    __syncthreads();
    int prev = red[0];

    if (gid < N) g_off[gid] = prev + sh[threadIdx.x] - v;
}

// ===========================================================================
// permute: atomic-free. p = off[dst[e]] + rank[e]; esrc[p] = src[e].
// ===========================================================================
__global__ __launch_bounds__(256) void permute_kernel(
    const int* __restrict__ src, const int* __restrict__ dst, int E)
{
    int t = blockIdx.x * 256 + threadIdx.x;
    int e = t * 4;
    if (e + 3 < E) {
        int4 d = *reinterpret_cast<const int4*>(dst + e);
        short4 r = *reinterpret_cast<const short4*>(g_rank + e);
        int4 s = *reinterpret_cast<const int4*>(src + e);
        int p0 = __ldg(&g_off[d.x]) + (int)(unsigned short)r.x;
        int p1 = __ldg(&g_off[d.y]) + (int)(unsigned short)r.y;
        int p2 = __ldg(&g_off[d.z]) + (int)(unsigned short)r.z;
        int p3 = __ldg(&g_off[d.w]) + (int)(unsigned short)r.w;
        g_esrc[p0] = s.x;
        g_esrc[p1] = s.y;
        g_esrc[p2] = s.z;
        g_esrc[p3] = s.w;
    } else {
        for (; e < E; e++) {
            int d = __ldg(dst + e);
            g_esrc[__ldg(&g_off[d]) + (int)g_rank[e]] = __ldg(src + e);
        }
    }
}

// ===========================================================================
// agg1: layer-1 aggregate. FOUR nodes per warp, 8 lanes each. Per-GROUP loop
// count (divergent groups; no shfl-max) with group-local shfl masks; feature
// loads predicated on w!=0 -> zero wasted wavefronts.
// ===========================================================================
__global__ __launch_bounds__(256) void agg1_kernel(const float* __restrict__ b1, int N)
{
    int wid = (blockIdx.x * 256 + threadIdx.x) >> 5;
    int lane = threadIdx.x & 31;
    int quad = lane >> 3;
    int l8 = lane & 7;
    int n = wid * 4 + quad;
    if (wid * 4 >= N) return;
    bool nvalid = (n < N);
    int nn = nvalid ? n : (N - 1);
    unsigned gmask = 0xFFu << (quad * 8);

    float ald = __ldg(&g_ald1[nn]);
    int start = g_off[nn];
    int deg = nvalid ? g_deg[nn] : 0;
    int end = start + deg;
    int nb = (deg + 7) >> 3;          // per-group trip count

    int s = 0; float w;
    {
        int idx = start + l8;
        bool v = idx < end;
        float al = 0.f;
        if (v) { s = __ldg(&g_esrc[idx]); al = __ldg(&g_als1[s]); }
        w = v ? __expf(leaky(al + ald)) : 0.f;
    }

    float4 acc = make_float4(0.f, 0.f, 0.f, 0.f);
    float den = 0.f;
    const uint2* h1u = reinterpret_cast<const uint2*>(g_h1h);
    for (int b = 0; b < nb; b++) {
        int idx2 = start + (b + 1) * 8 + l8;
        bool v2 = idx2 < end;
        int s2 = 0; float al2 = 0.f;
        if (v2) { s2 = __ldg(&g_esrc[idx2]); al2 = __ldg(&g_als1[s2]); }

        den += w;
#pragma unroll
        for (int j = 0; j < 8; j += 4) {
            int   s0 = __shfl_sync(gmask, s, j,     8);
            int   s1 = __shfl_sync(gmask, s, j + 1, 8);
            int   s2b= __shfl_sync(gmask, s, j + 2, 8);
            int   s3 = __shfl_sync(gmask, s, j + 3, 8);
            float w0 = __shfl_sync(gmask, w, j,     8);
            float w1 = __shfl_sync(gmask, w, j + 1, 8);
            float w2 = __shfl_sync(gmask, w, j + 2, 8);
            float w3 = __shfl_sync(gmask, w, j + 3, 8);
            uint2 z = make_uint2(0u, 0u);
            uint2 v0 = (w0 != 0.f) ? __ldg(&h1u[s0 * 8 + l8]) : z;
            uint2 v1 = (w1 != 0.f) ? __ldg(&h1u[s1 * 8 + l8]) : z;
            uint2 v2b= (w2 != 0.f) ? __ldg(&h1u[s2b* 8 + l8]) : z;
            uint2 v3 = (w3 != 0.f) ? __ldg(&h1u[s3 * 8 + l8]) : z;
            float2 f0a = h2f(v0.x), f0b = h2f(v0.y);
            float2 f1a = h2f(v1.x), f1b = h2f(v1.y);
            float2 f2a = h2f(v2b.x), f2b = h2f(v2b.y);
            float2 f3a = h2f(v3.x), f3b = h2f(v3.y);
            acc.x = fmaf(w0, f0a.x, acc.x); acc.y = fmaf(w0, f0a.y, acc.y);
            acc.z = fmaf(w0, f0b.x, acc.z); acc.w = fmaf(w0, f0b.y, acc.w);
            acc.x = fmaf(w1, f1a.x, acc.x); acc.y = fmaf(w1, f1a.y, acc.y);
            acc.z = fmaf(w1, f1b.x, acc.z); acc.w = fmaf(w1, f1b.y, acc.w);
            acc.x = fmaf(w2, f2a.x, acc.x); acc.y = fmaf(w2, f2a.y, acc.y);
            acc.z = fmaf(w2, f2b.x, acc.z); acc.w = fmaf(w2, f2b.y, acc.w);
            acc.x = fmaf(w3, f3a.x, acc.x); acc.y = fmaf(w3, f3a.y, acc.y);
            acc.z = fmaf(w3, f3b.x, acc.z); acc.w = fmaf(w3, f3b.y, acc.w);
        }
        s = s2;
        w = v2 ? __expf(leaky(al2 + ald)) : 0.f;
    }
#pragma unroll
    for (int o = 4; o; o >>= 1) den += __shfl_xor_sync(0xffffffffu, den, o, 8);

    float wself = __expf(leaky(__ldg(&g_als1[nn]) + ald));
    den += wself;
    {
        uint2 vo = __ldg(&h1u[nn * 8 + l8]);
        float2 fa = h2f(vo.x), fb = h2f(vo.y);
        acc.x = fmaf(wself, fa.x, acc.x); acc.y = fmaf(wself, fa.y, acc.y);
        acc.z = fmaf(wself, fb.x, acc.z); acc.w = fmaf(wself, fb.y, acc.w);
    }

    float inv = 1.0f / (den + 1e-16f);
    if (nvalid) {
        float4 bv = __ldg(&reinterpret_cast<const float4*>(b1)[l8]);
        float4 r;
        r.x = fmaxf(fmaf(acc.x, inv, bv.x), 0.f);
        r.y = fmaxf(fmaf(acc.y, inv, bv.y), 0.f);
        r.z = fmaxf(fmaf(acc.z, inv, bv.z), 0.f);
        r.w = fmaxf(fmaf(acc.w, inv, bv.w), 0.f);
        reinterpret_cast<float4*>(&g_hp1[n * 32])[l8] = r;
    }
}

// ===========================================================================
// node2: h2 = h' @ W2 (-> fp16); al_s2/al_d2
// ===========================================================================
__global__ __launch_bounds__(256) void node2_kernel(
    const float* __restrict__ W2,
    const float* __restrict__ asrc, const float* __restrict__ adst, int N)
{
    __shared__ float Ws[32 * 16];
    __shared__ float s_as[16], s_ad[16];
    for (int i = threadIdx.x; i < 32 * 16; i += 256) Ws[i] = W2[i];
    if (threadIdx.x < 16) { s_as[threadIdx.x] = asrc[threadIdx.x]; s_ad[threadIdx.x] = adst[threadIdx.x]; }
    __syncthreads();

    int n = blockIdx.x * 256 + threadIdx.x;
    if (n >= N) return;

    float4 h2[4];
#pragma unroll
    for (int i = 0; i < 4; i++) h2[i] = make_float4(0.f, 0.f, 0.f, 0.f);

    const float4* hp = reinterpret_cast<const float4*>(&g_hp1[n * 32]);
#pragma unroll
    for (int c4 = 0; c4 < 8; c4++) {
        float4 xv = hp[c4];
        float xk[4] = {xv.x, xv.y, xv.z, xv.w};
#pragma unroll
        for (int kk = 0; kk < 4; kk++) {
            const float4* wr = reinterpret_cast<const float4*>(&Ws[(c4 * 4 + kk) * 16]);
            float xs = xk[kk];
#pragma unroll
            for (int o4 = 0; o4 < 4; o4++) {
                float4 w = wr[o4];
                h2[o4].x = fmaf(xs, w.x, h2[o4].x); h2[o4].y = fmaf(xs, w.y, h2[o4].y);
                h2[o4].z = fmaf(xs, w.z, h2[o4].z); h2[o4].w = fmaf(xs, w.w, h2[o4].w);
            }
        }
    }

    float als = 0.f, ald = 0.f;
#pragma unroll
    for (int o4 = 0; o4 < 4; o4++) {
        float4 a  = h2[o4];
        float4 s4 = reinterpret_cast<const float4*>(s_as)[o4];
        float4 d4 = reinterpret_cast<const float4*>(s_ad)[o4];
        als += a.x*s4.x + a.y*s4.y + a.z*s4.z + a.w*s4.w;
        ald += a.x*d4.x + a.y*d4.y + a.z*d4.z + a.w*d4.w;
    }
    g_als2[n] = als; g_ald2[n] = ald;

    __half2* out = reinterpret_cast<__half2*>(&g_h2h[n * 16]);
#pragma unroll
    for (int o4 = 0; o4 < 4; o4++) {
        out[o4 * 2]     = __floats2half2_rn(h2[o4].x, h2[o4].y);
        out[o4 * 2 + 1] = __floats2half2_rn(h2[o4].z, h2[o4].w);
    }
}

// ===========================================================================
// agg2: layer-2 aggregate + output. EIGHT nodes per warp, 4 lanes each.
// Per-group loop count, group-local masks, predicated loads.
// ===========================================================================
__global__ __launch_bounds__(256) void agg2_kernel(
    const float* __restrict__ b2, float* __restrict__ out, int N)
{
    int wid = (blockIdx.x * 256 + threadIdx.x) >> 5;
    int lane = threadIdx.x & 31;
    int oct = lane >> 2;
    int l4 = lane & 3;
    int n = wid * 8 + oct;
    if (wid * 8 >= N) return;
    bool nvalid = (n < N);
    int nn = nvalid ? n : (N - 1);
    unsigned gmask = 0xFu << (oct * 4);

    float ald = __ldg(&g_ald2[nn]);
    int start = g_off[nn];
    int deg = nvalid ? g_deg[nn] : 0;
    int end = start + deg;
    int nb = (deg + 3) >> 2;          // per-group trip count

    int s = 0; float w;
    {
        int idx = start + l4;
        bool v = idx < end;
        float al = 0.f;
        if (v) { s = __ldg(&g_esrc[idx]); al = __ldg(&g_als2[s]); }
        w = v ? __expf(leaky(al + ald)) : 0.f;
    }

    float4 acc = make_float4(0.f, 0.f, 0.f, 0.f);
    float den = 0.f;
    const uint2* h2u = reinterpret_cast<const uint2*>(g_h2h);
    for (int b = 0; b < nb; b++) {
        int idx2 = start + (b + 1) * 4 + l4;
        bool v2 = idx2 < end;
        int s2 = 0; float al2 = 0.f;
        if (v2) { s2 = __ldg(&g_esrc[idx2]); al2 = __ldg(&g_als2[s2]); }

        den += w;
        {
            int   s0 = __shfl_sync(gmask, s, 0, 4);
            int   s1 = __shfl_sync(gmask, s, 1, 4);
            int   s2b= __shfl_sync(gmask, s, 2, 4);
            int   s3 = __shfl_sync(gmask, s, 3, 4);
            float w0 = __shfl_sync(gmask, w, 0, 4);
            float w1 = __shfl_sync(gmask, w, 1, 4);
            float w2 = __shfl_sync(gmask, w, 2, 4);
            float w3 = __shfl_sync(gmask, w, 3, 4);
            uint2 z = make_uint2(0u, 0u);
            uint2 v0 = (w0 != 0.f) ? __ldg(&h2u[s0 * 4 + l4]) : z;
            uint2 v1 = (w1 != 0.f) ? __ldg(&h2u[s1 * 4 + l4]) : z;
            uint2 v2b= (w2 != 0.f) ? __ldg(&h2u[s2b* 4 + l4]) : z;
            uint2 v3 = (w3 != 0.f) ? __ldg(&h2u[s3 * 4 + l4]) : z;
            float2 f0a = h2f(v0.x), f0b = h2f(v0.y);
            float2 f1a = h2f(v1.x), f1b = h2f(v1.y);
            float2 f2a = h2f(v2b.x), f2b = h2f(v2b.y);
            float2 f3a = h2f(v3.x), f3b = h2f(v3.y);
            acc.x = fmaf(w0, f0a.x, acc.x); acc.y = fmaf(w0, f0a.y, acc.y);
            acc.z = fmaf(w0, f0b.x, acc.z); acc.w = fmaf(w0, f0b.y, acc.w);
            acc.x = fmaf(w1, f1a.x, acc.x); acc.y = fmaf(w1, f1a.y, acc.y);
            acc.z = fmaf(w1, f1b.x, acc.z); acc.w = fmaf(w1, f1b.y, acc.w);
            acc.x = fmaf(w2, f2a.x, acc.x); acc.y = fmaf(w2, f2a.y, acc.y);
            acc.z = fmaf(w2, f2b.x, acc.z); acc.w = fmaf(w2, f2b.y, acc.w);
            acc.x = fmaf(w3, f3a.x, acc.x); acc.y = fmaf(w3, f3a.y, acc.y);
            acc.z = fmaf(w3, f3b.x, acc.z); acc.w = fmaf(w3, f3b.y, acc.w);
        }
        s = s2;
        w = v2 ? __expf(leaky(al2 + ald)) : 0.f;
    }
#pragma unroll
    for (int o = 2; o; o >>= 1) den += __shfl_xor_sync(0xffffffffu, den, o, 4);

    float wself = __expf(leaky(__ldg(&g_als2[nn]) + ald));
    den += wself;
    {
        uint2 vo = __ldg(&h2u[nn * 4 + l4]);
        float2 fa = h2f(vo.x), fb = h2f(vo.y);
        acc.x = fmaf(wself, fa.x, acc.x); acc.y = fmaf(wself, fa.y, acc.y);
        acc.z = fmaf(wself, fb.x, acc.z); acc.w = fmaf(wself, fb.y, acc.w);
    }

    float inv = 1.0f / (den + 1e-16f);
    if (nvalid) {
        float4 bv = __ldg(&reinterpret_cast<const float4*>(b2)[l4]);
        float4 r;
        r.x = fmaf(acc.x, inv, bv.x);
        r.y = fmaf(acc.y, inv, bv.y);
        r.z = fmaf(acc.z, inv, bv.z);
        r.w = fmaf(acc.w, inv, bv.w);
        reinterpret_cast<float4*>(&out[n * 16])[l4] = r;
    }
}

// ===========================================================================
extern "C" void kernel_launch(void* const* d_in, const int* in_sizes, int n_in,
                              void* d_out, int out_size)
{
    const float* x   = (const float*)d_in[0];
    const int*   ei  = (const int*)  d_in[1];
    const float* W1  = (const float*)d_in[3];
    const float* as1 = (const float*)d_in[4];
    const float* ad1 = (const float*)d_in[5];
    const float* b1  = (const float*)d_in[6];
    const float* W2  = (const float*)d_in[7];
    const float* as2 = (const float*)d_in[8];
    const float* ad2 = (const float*)d_in[9];
    const float* b2  = (const float*)d_in[10];

    int N = in_sizes[0] / 128;
    int E = in_sizes[1] / 2;
    const int* src = ei;
    const int* dst = ei + E;

    // single memset covers deg[NMAX] histogram + scan arrive counter
    void* p_deg = nullptr; cudaGetSymbolAddress(&p_deg, g_deg);
    cudaMemsetAsync(p_deg, 0, (size_t)(NMAX + 1) * sizeof(int));

    int nblkN = (N + 255) / 256;
    int nblkE4 = (E / 4 + 256) / 256;
    int nscan = (N + SCAN_B - 1) / SCAN_B;   // 98 <= 148: all-resident spin safe

    hist_node1_kernel<<<nblkE4 + nblkN, 256>>>(dst, E, x, W1, as1, ad1, N, nblkE4);
    scan_kernel<<<nscan, SCAN_B>>>(N, nscan);
    permute_kernel<<<nblkE4, 256>>>(src, dst, E);

    int nwarp1 = (((N + 3) / 4) * 32 + 255) / 256;
    agg1_kernel<<<nwarp1, 256>>>(b1, N);

    node2_kernel<<<nblkN, 256>>>(W2, as2, ad2, N);

    int nwarp2 = (((N + 7) / 8) * 32 + 255) / 256;
    agg2_kernel<<<nwarp2, 256>>>(b2, (float*)d_out, N);
}